// round 2
// baseline (speedup 1.0000x reference)
#include <cuda_runtime.h>

// HQQ grouped GEMM, Round 1: SIMT fp32 with f32x2 packed FMAs.
// Shapes (fixed by problem): E=8, K=1024, OUT=2816, GS=64, N=2048.
#define NE 8
#define KDIM 1024
#define ODIM 2816
#define GSZ 64
#define NTOK 2048

#define BM 128
#define BN 128
#define BK 16
#define NKT (KDIM / BK)

// ---- f32x2 packed helpers (Blackwell) ----
__device__ __forceinline__ unsigned long long pack2(float x) {
    unsigned long long r;
    unsigned int u = __float_as_uint(x);
    asm("mov.b64 %0, {%1, %2};" : "=l"(r) : "r"(u), "r"(u));
    return r;
}
__device__ __forceinline__ void ffma2(unsigned long long& d,
                                      unsigned long long a,
                                      unsigned long long b) {
    asm("fma.rn.f32x2 %0, %1, %2, %0;" : "+l"(d) : "l"(a), "l"(b));
}
__device__ __forceinline__ float2 unpack2(unsigned long long v) {
    unsigned int lo, hi;
    asm("mov.b64 {%0, %1}, %2;" : "=r"(lo), "=r"(hi) : "l"(v));
    return make_float2(__uint_as_float(lo), __uint_as_float(hi));
}

union F4U { float4 f; unsigned long long u[2]; };

__global__ __launch_bounds__(256, 2)
void hqq_grouped_gemm(const float* __restrict__ X,
                      const int* __restrict__ tpe,
                      const int* __restrict__ Wq,
                      const float* __restrict__ Sc,
                      const float* __restrict__ Zr,
                      float* __restrict__ Y)
{
    __shared__ __align__(16) float Xs[BK][BM + 4];  // transposed X tile (k-major)
    __shared__ __align__(16) float Ws[BK][BN];      // dequantized W tile

    const int tid = threadIdx.x;
    const int tx = tid & 15;   // n-direction, 16 threads
    const int ty = tid >> 4;   // m-direction, 16 threads
    const int m0 = blockIdx.y * BM;
    const int n0 = blockIdx.x * BN;

    // Expert boundaries (E=8, uniform across CTA; LDG through L1).
    int bnd[NE + 1];
    bnd[0] = 0;
#pragma unroll
    for (int e = 0; e < NE; ++e) bnd[e + 1] = bnd[e] + tpe[e];

    // Loader index maps.
    const int xrow = tid >> 2;        // 0..63  (two passes: +0, +64)
    const int xc   = (tid & 3) * 4;   // k-offset within tile: 0,4,8,12
    const int wrow = tid >> 5;        // 0..7   (two passes: +0, +8)
    const int wc   = (tid & 31) * 4;  // n-offset within tile: 0..124

    for (int e = 0; e < NE; ++e) {
        const int sLo = max(bnd[e], m0);
        const int sHi = min(bnd[e + 1], m0 + BM);
        if (sLo >= sHi) continue;   // expert has no rows in this m-tile

        const int*   Wb = Wq + e * (KDIM * ODIM) + n0;
        const float* Sb = Sc + e * ((KDIM / GSZ) * ODIM) + n0;
        const float* Zb = Zr + e * ((KDIM / GSZ) * ODIM) + n0;

        unsigned long long acc[8][4];
#pragma unroll
        for (int i = 0; i < 8; ++i)
#pragma unroll
            for (int j = 0; j < 4; ++j) acc[i][j] = 0ull;

        // Prefetch K-tile 0 into registers.
        float4 xr0 = *(const float4*)(X + (m0 + xrow) * KDIM + xc);
        float4 xr1 = *(const float4*)(X + (m0 + xrow + 64) * KDIM + xc);
        int4   wr0 = *(const int4*)(Wb + wrow * ODIM + wc);
        int4   wr1 = *(const int4*)(Wb + (wrow + 8) * ODIM + wc);

        for (int t = 0; t < NKT; ++t) {
            // Quant group is constant inside a 16-wide k-tile (16 | 64).
            const int g = (t * BK) >> 6;
            const float4 s4 = *(const float4*)(Sb + g * ODIM + wc);
            const float4 z4 = *(const float4*)(Zb + g * ODIM + wc);

            // Store X transposed.
            Xs[xc + 0][xrow] = xr0.x;
            Xs[xc + 1][xrow] = xr0.y;
            Xs[xc + 2][xrow] = xr0.z;
            Xs[xc + 3][xrow] = xr0.w;
            Xs[xc + 0][xrow + 64] = xr1.x;
            Xs[xc + 1][xrow + 64] = xr1.y;
            Xs[xc + 2][xrow + 64] = xr1.z;
            Xs[xc + 3][xrow + 64] = xr1.w;

            // Dequantize W at SMEM store: w = (q - zero) * scale.
            float4 w0, w1;
            w0.x = ((float)wr0.x - z4.x) * s4.x;
            w0.y = ((float)wr0.y - z4.y) * s4.y;
            w0.z = ((float)wr0.z - z4.z) * s4.z;
            w0.w = ((float)wr0.w - z4.w) * s4.w;
            w1.x = ((float)wr1.x - z4.x) * s4.x;
            w1.y = ((float)wr1.y - z4.y) * s4.y;
            w1.z = ((float)wr1.z - z4.z) * s4.z;
            w1.w = ((float)wr1.w - z4.w) * s4.w;
            *(float4*)&Ws[wrow][wc]     = w0;
            *(float4*)&Ws[wrow + 8][wc] = w1;

            __syncthreads();

            // Prefetch next K-tile while computing this one.
            if (t + 1 < NKT) {
                const int k1 = (t + 1) * BK;
                xr0 = *(const float4*)(X + (m0 + xrow) * KDIM + k1 + xc);
                xr1 = *(const float4*)(X + (m0 + xrow + 64) * KDIM + k1 + xc);
                wr0 = *(const int4*)(Wb + (k1 + wrow) * ODIM + wc);
                wr1 = *(const int4*)(Wb + (k1 + wrow + 8) * ODIM + wc);
            }

#pragma unroll
            for (int kk = 0; kk < BK; ++kk) {
                // W fragment: two conflict-free LDS.128, bit-cast to f32x2 pairs.
                F4U wA, wB;
                wA.f = *(const float4*)&Ws[kk][tx * 4];
                wB.f = *(const float4*)&Ws[kk][64 + tx * 4];
                // X fragment: broadcast loads (2 distinct addrs/warp).
                const float4 xA = *(const float4*)&Xs[kk][ty * 8];
                const float4 xB = *(const float4*)&Xs[kk][ty * 8 + 4];
                unsigned long long xb[8];
                xb[0] = pack2(xA.x); xb[1] = pack2(xA.y);
                xb[2] = pack2(xA.z); xb[3] = pack2(xA.w);
                xb[4] = pack2(xB.x); xb[5] = pack2(xB.y);
                xb[6] = pack2(xB.z); xb[7] = pack2(xB.w);
#pragma unroll
                for (int mi = 0; mi < 8; ++mi) {
                    ffma2(acc[mi][0], xb[mi], wA.u[0]);
                    ffma2(acc[mi][1], xb[mi], wA.u[1]);
                    ffma2(acc[mi][2], xb[mi], wB.u[0]);
                    ffma2(acc[mi][3], xb[mi], wB.u[1]);
                }
            }
            __syncthreads();
        }

        // Store rows belonging to this expert's segment.
#pragma unroll
        for (int mi = 0; mi < 8; ++mi) {
            const int gm = m0 + ty * 8 + mi;
            if (gm >= sLo && gm < sHi) {
                float* yp = Y + gm * ODIM + n0 + tx * 4;
                float2 a = unpack2(acc[mi][0]);
                float2 b = unpack2(acc[mi][1]);
                float2 c = unpack2(acc[mi][2]);
                float2 d = unpack2(acc[mi][3]);
                *(float4*)yp        = make_float4(a.x, a.y, b.x, b.y);
                *(float4*)(yp + 64) = make_float4(c.x, c.y, d.x, d.y);
            }
        }
    }
}

extern "C" void kernel_launch(void* const* d_in, const int* in_sizes, int n_in,
                              void* d_out, int out_size) {
    const float* X   = (const float*)d_in[0];
    const int*   tpe = (const int*)d_in[1];
    const int*   Wq  = (const int*)d_in[2];
    const float* Sc  = (const float*)d_in[3];
    const float* Zr  = (const float*)d_in[4];
    float*       Y   = (float*)d_out;

    dim3 grid(ODIM / BN, NTOK / BM);  // 22 x 16
    hqq_grouped_gemm<<<grid, 256>>>(X, tpe, Wq, Sc, Zr, Y);
}

// round 4
// speedup vs baseline: 1.2722x; 1.2722x over previous
#include <cuda_runtime.h>
#include <cstdint>

// HQQ grouped GEMM via mma.sync bf16 3-pass (hi/lo split emulating fp32).
// E=8, K=1024, OUT=2816, GS=64, N=2048.
#define NE 8
#define KDIM 1024
#define ODIM 2816
#define NTOK 2048

#define BM 128
#define BN 128
#define BK 32
#define NKT (KDIM / BK)   // 32

#define XPITCH 40    // bf16 elems/row (80B)  -> conflict-free ldmatrix
#define WPITCH 136   // bf16 elems/row (272B) -> conflict-free ldmatrix.trans

// Split two fp32 into packed-bf16 hi word + packed-bf16 residual word.
// Word layout: low half = f0, high half = f1 (matches ascending-k memory order).
__device__ __forceinline__ void split2(float f0, float f1, uint32_t& hi, uint32_t& lo) {
    asm("cvt.rn.bf16x2.f32 %0, %1, %2;" : "=r"(hi) : "f"(f1), "f"(f0));
    float h0 = __uint_as_float(hi << 16);
    float h1 = __uint_as_float(hi & 0xffff0000u);
    asm("cvt.rn.bf16x2.f32 %0, %1, %2;" : "=r"(lo) : "f"(f1 - h1), "f"(f0 - h0));
}

#define LDSM4(r, a) asm volatile( \
    "ldmatrix.sync.aligned.m8n8.x4.shared.b16 {%0,%1,%2,%3}, [%4];" \
    : "=r"((r)[0]), "=r"((r)[1]), "=r"((r)[2]), "=r"((r)[3]) : "r"(a))
#define LDSM4T(r, a) asm volatile( \
    "ldmatrix.sync.aligned.m8n8.x4.trans.shared.b16 {%0,%1,%2,%3}, [%4];" \
    : "=r"((r)[0]), "=r"((r)[1]), "=r"((r)[2]), "=r"((r)[3]) : "r"(a))
#define MMA(d, a, b0, b1) asm volatile( \
    "mma.sync.aligned.m16n8k16.row.col.f32.bf16.bf16.f32 " \
    "{%0,%1,%2,%3}, {%4,%5,%6,%7}, {%8,%9}, {%0,%1,%2,%3};" \
    : "+f"((d)[0]), "+f"((d)[1]), "+f"((d)[2]), "+f"((d)[3]) \
    : "r"((a)[0]), "r"((a)[1]), "r"((a)[2]), "r"((a)[3]), "r"(b0), "r"(b1))

extern "C" __global__ void __launch_bounds__(256)
hqq_hmma_kernel(const float* __restrict__ X, const int* __restrict__ tpe,
                const int* __restrict__ Wq, const float* __restrict__ Sc,
                const float* __restrict__ Zr, float* __restrict__ Y)
{
    __shared__ __align__(16) uint16_t XhS[BM * XPITCH];
    __shared__ __align__(16) uint16_t XlS[BM * XPITCH];
    __shared__ __align__(16) uint16_t WhS[BK * WPITCH];
    __shared__ __align__(16) uint16_t WlS[BK * WPITCH];

    const int tid  = threadIdx.x;
    const int lane = tid & 31;
    const int wid  = tid >> 5;
    const int wm = (wid & 1) * 64;    // warp m-offset in CTA tile
    const int wn = (wid >> 1) * 32;   // warp n-offset in CTA tile
    const int n0 = blockIdx.x * BN;
    const int m0 = blockIdx.y * BM;

    int bnd[NE + 1];
    bnd[0] = 0;
#pragma unroll
    for (int e = 0; e < NE; ++e) bnd[e + 1] = bnd[e] + tpe[e];

    // loader maps
    const int xrow = tid >> 1;          // 0..127
    const int xk   = (tid & 1) * 16;    // 0 or 16
    const int wrow = tid >> 3;          // 0..31
    const int wnq  = (tid & 7) * 16;    // 0..112

    const uint32_t XhB = (uint32_t)__cvta_generic_to_shared(XhS);
    const uint32_t XlB = (uint32_t)__cvta_generic_to_shared(XlS);
    const uint32_t WhB = (uint32_t)__cvta_generic_to_shared(WhS);
    const uint32_t WlB = (uint32_t)__cvta_generic_to_shared(WlS);

    // ldmatrix lane addresses (k-step offset added at use)
    uint32_t aH[4], aL[4];
#pragma unroll
    for (int mi = 0; mi < 4; ++mi) {
        int r = wm + mi * 16 + (lane & 15);
        uint32_t off = (uint32_t)(r * (XPITCH * 2) + (lane >> 4) * 16);
        aH[mi] = XhB + off;
        aL[mi] = XlB + off;
    }
    uint32_t bHa[2], bLa[2];
#pragma unroll
    for (int nb = 0; nb < 2; ++nb) {
        uint32_t off = (uint32_t)((lane & 15) * (WPITCH * 2) +
                                  (wn + nb * 16 + (lane >> 4) * 8) * 2);
        bHa[nb] = WhB + off;
        bLa[nb] = WlB + off;
    }

    for (int e = 0; e < NE; ++e) {
        const int sLo = max(bnd[e], m0);
        const int sHi = min(bnd[e + 1], m0 + BM);
        if (sLo >= sHi) continue;

        const int*   Wb = Wq + (size_t)e * KDIM * ODIM + n0;
        const float* Sb = Sc + (size_t)e * (KDIM / 64) * ODIM + n0;
        const float* Zb = Zr + (size_t)e * (KDIM / 64) * ODIM + n0;

        float acc[4][4][4];
#pragma unroll
        for (int i = 0; i < 4; ++i)
#pragma unroll
            for (int j = 0; j < 4; ++j)
#pragma unroll
                for (int r = 0; r < 4; ++r) acc[i][j][r] = 0.f;

        // register-stage tile 0
        const float* Xp = X + (size_t)(m0 + xrow) * KDIM + xk;
        float4 xs[4];
        int4   wsv[4];
#pragma unroll
        for (int j = 0; j < 4; ++j) xs[j] = *(const float4*)(Xp + j * 4);
#pragma unroll
        for (int j = 0; j < 4; ++j)
            wsv[j] = *(const int4*)(Wb + (size_t)wrow * ODIM + wnq + j * 4);

        for (int t = 0; t < NKT; ++t) {
            const int g = t >> 1;  // quant group (GS=64, BK=32)

            // ---- store X tiles (hi/lo split) ----
            {
                uint32_t h[8], l[8];
#pragma unroll
                for (int j = 0; j < 4; ++j) {
                    split2(xs[j].x, xs[j].y, h[2 * j], l[2 * j]);
                    split2(xs[j].z, xs[j].w, h[2 * j + 1], l[2 * j + 1]);
                }
                uint16_t* dh = &XhS[xrow * XPITCH + xk];
                uint16_t* dl = &XlS[xrow * XPITCH + xk];
                *(uint4*)dh       = make_uint4(h[0], h[1], h[2], h[3]);
                *(uint4*)(dh + 8) = make_uint4(h[4], h[5], h[6], h[7]);
                *(uint4*)dl       = make_uint4(l[0], l[1], l[2], l[3]);
                *(uint4*)(dl + 8) = make_uint4(l[4], l[5], l[6], l[7]);
            }
            // ---- dequant + store W tiles (hi/lo split) ----
            {
                uint32_t h[8], l[8];
                const float* Sp = Sb + (size_t)g * ODIM + wnq;
                const float* Zp = Zb + (size_t)g * ODIM + wnq;
#pragma unroll
                for (int j = 0; j < 4; ++j) {
                    float4 s4 = *(const float4*)(Sp + j * 4);
                    float4 z4 = *(const float4*)(Zp + j * 4);
                    float w0 = ((float)wsv[j].x - z4.x) * s4.x;
                    float w1 = ((float)wsv[j].y - z4.y) * s4.y;
                    float w2 = ((float)wsv[j].z - z4.z) * s4.z;
                    float w3 = ((float)wsv[j].w - z4.w) * s4.w;
                    split2(w0, w1, h[2 * j], l[2 * j]);
                    split2(w2, w3, h[2 * j + 1], l[2 * j + 1]);
                }
                uint16_t* dh = &WhS[wrow * WPITCH + wnq];
                uint16_t* dl = &WlS[wrow * WPITCH + wnq];
                *(uint4*)dh       = make_uint4(h[0], h[1], h[2], h[3]);
                *(uint4*)(dh + 8) = make_uint4(h[4], h[5], h[6], h[7]);
                *(uint4*)dl       = make_uint4(l[0], l[1], l[2], l[3]);
                *(uint4*)(dl + 8) = make_uint4(l[4], l[5], l[6], l[7]);
            }
            __syncthreads();

            // ---- prefetch next tile (overlaps MMA block below) ----
            if (t + 1 < NKT) {
                const int kb = (t + 1) * BK;
#pragma unroll
                for (int j = 0; j < 4; ++j) xs[j] = *(const float4*)(Xp + kb + j * 4);
#pragma unroll
                for (int j = 0; j < 4; ++j)
                    wsv[j] = *(const int4*)(Wb + (size_t)(kb + wrow) * ODIM + wnq + j * 4);
            }

            // ---- 2 k-steps x 3 passes of mma ----
#pragma unroll
            for (int s = 0; s < 2; ++s) {
                const uint32_t aoff = (uint32_t)(s * 32);
                const uint32_t boff = (uint32_t)(s * 16 * WPITCH * 2);
                uint32_t Ah[4][4], Al[4][4], Bv[2][4], Bl[2][4];
#pragma unroll
                for (int mi = 0; mi < 4; ++mi) LDSM4(Ah[mi], aH[mi] + aoff);
#pragma unroll
                for (int nb = 0; nb < 2; ++nb) LDSM4T(Bv[nb], bHa[nb] + boff);
#pragma unroll
                for (int mi = 0; mi < 4; ++mi)
#pragma unroll
                    for (int nj = 0; nj < 4; ++nj)
                        MMA(acc[mi][nj], Ah[mi],
                            Bv[nj >> 1][(nj & 1) * 2], Bv[nj >> 1][(nj & 1) * 2 + 1]);
#pragma unroll
                for (int mi = 0; mi < 4; ++mi) LDSM4(Al[mi], aL[mi] + aoff);
#pragma unroll
                for (int mi = 0; mi < 4; ++mi)
#pragma unroll
                    for (int nj = 0; nj < 4; ++nj)
                        MMA(acc[mi][nj], Al[mi],
                            Bv[nj >> 1][(nj & 1) * 2], Bv[nj >> 1][(nj & 1) * 2 + 1]);
#pragma unroll
                for (int nb = 0; nb < 2; ++nb) LDSM4T(Bl[nb], bLa[nb] + boff);
#pragma unroll
                for (int mi = 0; mi < 4; ++mi)
#pragma unroll
                    for (int nj = 0; nj < 4; ++nj)
                        MMA(acc[mi][nj], Ah[mi],
                            Bl[nj >> 1][(nj & 1) * 2], Bl[nj >> 1][(nj & 1) * 2 + 1]);
            }
            __syncthreads();
        }

        // ---- epilogue: masked store of this expert's rows ----
        const int rbase = m0 + wm + (lane >> 2);
        const int cbase = n0 + wn + (lane & 3) * 2;
#pragma unroll
        for (int mi = 0; mi < 4; ++mi) {
#pragma unroll
            for (int nj = 0; nj < 4; ++nj) {
                const int r0 = rbase + mi * 16;
                const int c  = cbase + nj * 8;
                if (r0 >= sLo && r0 < sHi)
                    *(float2*)(Y + (size_t)r0 * ODIM + c) =
                        make_float2(acc[mi][nj][0], acc[mi][nj][1]);
                const int r1 = r0 + 8;
                if (r1 >= sLo && r1 < sHi)
                    *(float2*)(Y + (size_t)r1 * ODIM + c) =
                        make_float2(acc[mi][nj][2], acc[mi][nj][3]);
            }
        }
    }
}

extern "C" void kernel_launch(void* const* d_in, const int* in_sizes, int n_in,
                              void* d_out, int out_size) {
    const float* X   = (const float*)d_in[0];
    const int*   tpe = (const int*)d_in[1];
    const int*   Wq  = (const int*)d_in[2];
    const float* Sc  = (const float*)d_in[3];
    const float* Zr  = (const float*)d_in[4];
    float*       Y   = (float*)d_out;

    dim3 grid(ODIM / BN, NTOK / BM);  // 22 x 16
    hqq_hmma_kernel<<<grid, 256>>>(X, tpe, Wq, Sc, Zr, Y);
}

// round 5
// speedup vs baseline: 1.7262x; 1.3569x over previous
#include <cuda_runtime.h>
#include <cstdint>

// HQQ grouped GEMM: 2-pass bf16 mma.sync with deferred group scales.
// y = sum_g s_g*(x.q)_g  -  sum_g s_g*z_g*T_g,   T = per-group rowsums of x.
// E=8, K=1024, OUT=2816, GS=64, N=2048.
#define NE 8
#define KDIM 1024
#define ODIM 2816
#define NTOK 2048
#define GD 16           // KDIM/64 quant groups

#define BM 128
#define BN 64
#define BK 32
#define NKT (KDIM / BK) // 32

static __device__ float T_buf[NTOK * GD];

// ---------------- kernel A: per-group rowsums T[n,g] ----------------
__global__ void __launch_bounds__(256) rowsum_k(const float* __restrict__ X) {
    const int row = blockIdx.x * 4 + (threadIdx.x >> 6);
    const int p = threadIdx.x & 63;              // 16 floats each, within one group
    const float4* xp = (const float4*)(X + (size_t)row * KDIM + p * 16);
    float s = 0.f;
#pragma unroll
    for (int i = 0; i < 4; ++i) { float4 v = xp[i]; s += (v.x + v.y) + (v.z + v.w); }
    s += __shfl_xor_sync(0xffffffffu, s, 1);
    s += __shfl_xor_sync(0xffffffffu, s, 2);
    const int lane = threadIdx.x & 31;
    if ((lane & 3) == 0)
        T_buf[row * GD + ((threadIdx.x >> 5) & 1) * 8 + (lane >> 2)] = s;
}

// ---------------- kernel B: Y = - sum_g (s*z)[g,o] * T[n,g] ----------------
__global__ void __launch_bounds__(256) yinit_k(const int* __restrict__ tpe,
                                               const float* __restrict__ Sc,
                                               const float* __restrict__ Zr,
                                               float* __restrict__ Y) {
    __shared__ float Ts[128 * GD];
    const int tid = threadIdx.x;
    const int n0 = blockIdx.x * 128;
    const int m0 = blockIdx.y * 128;
    *(float4*)&Ts[tid * 8]     = *(const float4*)&T_buf[m0 * GD + tid * 8];
    *(float4*)&Ts[tid * 8 + 4] = *(const float4*)&T_buf[m0 * GD + tid * 8 + 4];
    __syncthreads();
    const int c0 = (tid & 31) * 4;
    const int rb = (tid >> 5) * 16;
    int cum = 0;
    for (int e = 0; e < NE; ++e) {
        const int lo = cum; cum += tpe[e];
        const int sLo = max(lo, m0), sHi = min(cum, m0 + 128);
        if (sLo >= sHi) continue;
        const float* Sp = Sc + (size_t)e * GD * ODIM + n0 + c0;
        const float* Zp = Zr + (size_t)e * GD * ODIM + n0 + c0;
        float y[16][4];
#pragma unroll
        for (int i = 0; i < 16; ++i) y[i][0] = y[i][1] = y[i][2] = y[i][3] = 0.f;
#pragma unroll
        for (int g = 0; g < GD; ++g) {
            const float4 s4 = *(const float4*)(Sp + (size_t)g * ODIM);
            const float4 z4 = *(const float4*)(Zp + (size_t)g * ODIM);
            const float4 u = make_float4(s4.x * z4.x, s4.y * z4.y,
                                         s4.z * z4.z, s4.w * z4.w);
#pragma unroll
            for (int i = 0; i < 16; ++i) {
                const float tv = Ts[(rb + i) * GD + g];
                y[i][0] -= u.x * tv; y[i][1] -= u.y * tv;
                y[i][2] -= u.z * tv; y[i][3] -= u.w * tv;
            }
        }
#pragma unroll
        for (int i = 0; i < 16; ++i) {
            const int r = m0 + rb + i;
            if (r >= sLo && r < sHi)
                *(float4*)(Y + (size_t)r * ODIM + n0 + c0) = *(float4*)y[i];
        }
    }
}

// ---------------- main kernel ----------------
// Split fp32 -> packed bf16 hi word + bf16 residual word (low half = f0).
__device__ __forceinline__ void split2(float f0, float f1, uint32_t& hi, uint32_t& lo) {
    asm("cvt.rn.bf16x2.f32 %0, %1, %2;" : "=r"(hi) : "f"(f1), "f"(f0));
    float h0 = __uint_as_float(hi << 16);
    float h1 = __uint_as_float(hi & 0xffff0000u);
    asm("cvt.rn.bf16x2.f32 %0, %1, %2;" : "=r"(lo) : "f"(f1 - h1), "f"(f0 - h0));
}
__device__ __forceinline__ uint32_t cvt2q(int a, int b) {
    uint32_t r;
    asm("cvt.rn.bf16x2.f32 %0, %1, %2;" : "=r"(r) : "f"((float)b), "f"((float)a));
    return r;
}

#define LDSM4(r, a) asm volatile( \
    "ldmatrix.sync.aligned.m8n8.x4.shared.b16 {%0,%1,%2,%3}, [%4];" \
    : "=r"((r)[0]), "=r"((r)[1]), "=r"((r)[2]), "=r"((r)[3]) : "r"(a))
#define LDSM4T(r, a) asm volatile( \
    "ldmatrix.sync.aligned.m8n8.x4.trans.shared.b16 {%0,%1,%2,%3}, [%4];" \
    : "=r"((r)[0]), "=r"((r)[1]), "=r"((r)[2]), "=r"((r)[3]) : "r"(a))
#define MMA(d, a, b0, b1) asm volatile( \
    "mma.sync.aligned.m16n8k16.row.col.f32.bf16.bf16.f32 " \
    "{%0,%1,%2,%3}, {%4,%5,%6,%7}, {%8,%9}, {%0,%1,%2,%3};" \
    : "+f"((d)[0]), "+f"((d)[1]), "+f"((d)[2]), "+f"((d)[3]) \
    : "r"((a)[0]), "r"((a)[1]), "r"((a)[2]), "r"((a)[3]), "r"(b0), "r"(b1))
#define MMA_Z(d, a, b0, b1) asm volatile( \
    "mma.sync.aligned.m16n8k16.row.col.f32.bf16.bf16.f32 " \
    "{%0,%1,%2,%3}, {%4,%5,%6,%7}, {%8,%9}, {%10,%10,%10,%10};" \
    : "=f"((d)[0]), "=f"((d)[1]), "=f"((d)[2]), "=f"((d)[3]) \
    : "r"((a)[0]), "r"((a)[1]), "r"((a)[2]), "r"((a)[3]), "r"(b0), "r"(b1), \
      "f"(0.0f))

// smem layouts (chunk = 16B = 8 bf16):
//  X: 128 rows x 32 k, pitch 64B (4 chunks), swizzle c' = c ^ ((row>>1)&3)
//  W: 32 rows x 64 n, pitch 128B (8 chunks), swizzle c' = c ^ (row&7)
#define XBUF (BM * BK)      // bf16 elems per buffer
#define WBUF (BK * BN)

__global__ void __launch_bounds__(256, 2)
hqq_main(const float* __restrict__ X, const int* __restrict__ tpe,
         const int* __restrict__ Wq, const float* __restrict__ Sc,
         float* __restrict__ Y)
{
    __shared__ __align__(16) uint16_t XhS[2][XBUF];
    __shared__ __align__(16) uint16_t XlS[2][XBUF];
    __shared__ __align__(16) uint16_t WtS[2][WBUF];

    const int tid = threadIdx.x;
    const int lane = tid & 31;
    const int wid = tid >> 5;
    const int wm = (wid & 3) * 32;
    const int wn = (wid >> 2) * 32;
    const int n0 = blockIdx.x * BN;
    const int m0 = blockIdx.y * BM;

    const uint32_t XhB = (uint32_t)__cvta_generic_to_shared(XhS);
    const uint32_t XlB = (uint32_t)__cvta_generic_to_shared(XlS);
    const uint32_t WtB = (uint32_t)__cvta_generic_to_shared(WtS);

    // ldmatrix byte offsets (buffer-relative), constant over the loop.
    uint32_t aoff[2][2], boff[2][2];
#pragma unroll
    for (int mi = 0; mi < 2; ++mi)
#pragma unroll
        for (int s = 0; s < 2; ++s) {
            const int r = wm + mi * 16 + (lane & 15);
            const int c = s * 2 + (lane >> 4);
            aoff[mi][s] = (uint32_t)(r * 64 + ((c ^ ((r >> 1) & 3)) << 4));
        }
#pragma unroll
    for (int s = 0; s < 2; ++s)
#pragma unroll
        for (int nb = 0; nb < 2; ++nb) {
            const int r = s * 16 + (lane & 15);
            const int c = (wn >> 3) + nb * 2 + (lane >> 4);
            boff[s][nb] = (uint32_t)(r * 128 + ((c ^ (r & 7)) << 4));
        }

    // loader maps
    const int xrow = tid >> 1;
    const int xkc = (tid & 1) * 2;                 // chunk base (0 or 2)
    const float* Xp = X + (size_t)(m0 + xrow) * KDIM + (tid & 1) * 16;
    const uint32_t xsw0 = (uint32_t)(xrow * 64 + (((xkc + 0) ^ ((xrow >> 1) & 3)) << 4));
    const uint32_t xsw1 = (uint32_t)(xrow * 64 + (((xkc + 1) ^ ((xrow >> 1) & 3)) << 4));
    const int wrow = tid >> 3;
    const int wch = tid & 7;
    const uint32_t wsw = (uint32_t)(wrow * 128 + ((wch ^ (wrow & 7)) << 4));

    int cum = 0;
    for (int e = 0; e < NE; ++e) {
        const int lo = cum;
        cum += tpe[e];
        const int sLo = max(lo, m0), sHi = min(cum, m0 + BM);
        if (sLo >= sHi) continue;

        const int* Wb = Wq + (size_t)e * KDIM * ODIM + n0;
        const float* Sb = Sc + (size_t)e * GD * ODIM + n0;

        float acc[2][4][4];
#pragma unroll
        for (int i = 0; i < 2; ++i)
#pragma unroll
            for (int j = 0; j < 4; ++j)
#pragma unroll
                for (int r = 0; r < 4; ++r) acc[i][j][r] = 0.f;

        // ---- stage tile 0 ----
        float4 xs[4];
        int4 wv0, wv1;
#pragma unroll
        for (int j = 0; j < 4; ++j) xs[j] = *(const float4*)(Xp + j * 4);
        wv0 = *(const int4*)(Wb + (size_t)wrow * ODIM + wch * 8);
        wv1 = *(const int4*)(Wb + (size_t)wrow * ODIM + wch * 8 + 4);

        // store tile 0 -> buf 0
        {
            uint32_t h[8], l[8];
#pragma unroll
            for (int j = 0; j < 4; ++j) {
                split2(xs[j].x, xs[j].y, h[2 * j], l[2 * j]);
                split2(xs[j].z, xs[j].w, h[2 * j + 1], l[2 * j + 1]);
            }
            asm volatile("st.shared.v4.b32 [%0], {%1,%2,%3,%4};" ::
                         "r"(XhB + xsw0), "r"(h[0]), "r"(h[1]), "r"(h[2]), "r"(h[3]));
            asm volatile("st.shared.v4.b32 [%0], {%1,%2,%3,%4};" ::
                         "r"(XhB + xsw1), "r"(h[4]), "r"(h[5]), "r"(h[6]), "r"(h[7]));
            asm volatile("st.shared.v4.b32 [%0], {%1,%2,%3,%4};" ::
                         "r"(XlB + xsw0), "r"(l[0]), "r"(l[1]), "r"(l[2]), "r"(l[3]));
            asm volatile("st.shared.v4.b32 [%0], {%1,%2,%3,%4};" ::
                         "r"(XlB + xsw1), "r"(l[4]), "r"(l[5]), "r"(l[6]), "r"(l[7]));
            uint32_t q0 = cvt2q(wv0.x, wv0.y), q1 = cvt2q(wv0.z, wv0.w);
            uint32_t q2 = cvt2q(wv1.x, wv1.y), q3 = cvt2q(wv1.z, wv1.w);
            asm volatile("st.shared.v4.b32 [%0], {%1,%2,%3,%4};" ::
                         "r"(WtB + wsw), "r"(q0), "r"(q1), "r"(q2), "r"(q3));
        }
        __syncthreads();

        float2 s2[4];
        for (int t = 0; t < NKT; ++t) {
            const int bb = t & 1;
            const uint32_t XhBb = XhB + bb * (XBUF * 2);
            const uint32_t XlBb = XlB + bb * (XBUF * 2);
            const uint32_t WtBb = WtB + bb * (WBUF * 2);

            // issue global loads for tile t+1
            if (t + 1 < NKT) {
                const int kb = (t + 1) * BK;
#pragma unroll
                for (int j = 0; j < 4; ++j) xs[j] = *(const float4*)(Xp + kb + j * 4);
                wv0 = *(const int4*)(Wb + (size_t)(kb + wrow) * ODIM + wch * 8);
                wv1 = *(const int4*)(Wb + (size_t)(kb + wrow) * ODIM + wch * 8 + 4);
            }
            // group scales (shared by tile pair)
            if ((t & 1) == 0) {
                const int g = t >> 1;
#pragma unroll
                for (int nj = 0; nj < 4; ++nj)
                    s2[nj] = *(const float2*)(Sb + (size_t)g * ODIM + wn + nj * 8 +
                                              (lane & 3) * 2);
            }

            // ---- MMA: 2 k-steps x (hi + lo) into tacc ----
            float tacc[2][4][4];
#pragma unroll
            for (int s = 0; s < 2; ++s) {
                uint32_t Ah[2][4], Al[2][4], Bv[2][4];
                LDSM4(Ah[0], XhBb + aoff[0][s]);
                LDSM4(Ah[1], XhBb + aoff[1][s]);
                LDSM4T(Bv[0], WtBb + boff[s][0]);
                LDSM4T(Bv[1], WtBb + boff[s][1]);
                LDSM4(Al[0], XlBb + aoff[0][s]);
                LDSM4(Al[1], XlBb + aoff[1][s]);
#pragma unroll
                for (int mi = 0; mi < 2; ++mi)
#pragma unroll
                    for (int nj = 0; nj < 4; ++nj) {
                        const uint32_t b0 = Bv[nj >> 1][(nj & 1) * 2];
                        const uint32_t b1 = Bv[nj >> 1][(nj & 1) * 2 + 1];
                        if (s == 0) { MMA_Z(tacc[mi][nj], Ah[mi], b0, b1); }
                        else        { MMA(tacc[mi][nj], Ah[mi], b0, b1); }
                    }
#pragma unroll
                for (int mi = 0; mi < 2; ++mi)
#pragma unroll
                    for (int nj = 0; nj < 4; ++nj) {
                        const uint32_t b0 = Bv[nj >> 1][(nj & 1) * 2];
                        const uint32_t b1 = Bv[nj >> 1][(nj & 1) * 2 + 1];
                        MMA(tacc[mi][nj], Al[mi], b0, b1);
                    }
            }
            // fold group scale: acc += s * tacc
#pragma unroll
            for (int mi = 0; mi < 2; ++mi)
#pragma unroll
                for (int nj = 0; nj < 4; ++nj) {
                    acc[mi][nj][0] += s2[nj].x * tacc[mi][nj][0];
                    acc[mi][nj][1] += s2[nj].y * tacc[mi][nj][1];
                    acc[mi][nj][2] += s2[nj].x * tacc[mi][nj][2];
                    acc[mi][nj][3] += s2[nj].y * tacc[mi][nj][3];
                }

            // store tile t+1 into the other buffer
            if (t + 1 < NKT) {
                const uint32_t Xh2 = XhB + (1 - bb) * (XBUF * 2);
                const uint32_t Xl2 = XlB + (1 - bb) * (XBUF * 2);
                const uint32_t Wt2 = WtB + (1 - bb) * (WBUF * 2);
                uint32_t h[8], l[8];
#pragma unroll
                for (int j = 0; j < 4; ++j) {
                    split2(xs[j].x, xs[j].y, h[2 * j], l[2 * j]);
                    split2(xs[j].z, xs[j].w, h[2 * j + 1], l[2 * j + 1]);
                }
                asm volatile("st.shared.v4.b32 [%0], {%1,%2,%3,%4};" ::
                             "r"(Xh2 + xsw0), "r"(h[0]), "r"(h[1]), "r"(h[2]), "r"(h[3]));
                asm volatile("st.shared.v4.b32 [%0], {%1,%2,%3,%4};" ::
                             "r"(Xh2 + xsw1), "r"(h[4]), "r"(h[5]), "r"(h[6]), "r"(h[7]));
                asm volatile("st.shared.v4.b32 [%0], {%1,%2,%3,%4};" ::
                             "r"(Xl2 + xsw0), "r"(l[0]), "r"(l[1]), "r"(l[2]), "r"(l[3]));
                asm volatile("st.shared.v4.b32 [%0], {%1,%2,%3,%4};" ::
                             "r"(Xl2 + xsw1), "r"(l[4]), "r"(l[5]), "r"(l[6]), "r"(l[7]));
                uint32_t q0 = cvt2q(wv0.x, wv0.y), q1 = cvt2q(wv0.z, wv0.w);
                uint32_t q2 = cvt2q(wv1.x, wv1.y), q3 = cvt2q(wv1.z, wv1.w);
                asm volatile("st.shared.v4.b32 [%0], {%1,%2,%3,%4};" ::
                             "r"(Wt2 + wsw), "r"(q0), "r"(q1), "r"(q2), "r"(q3));
            }
            __syncthreads();
        }

        // ---- epilogue: Y += acc on this expert's rows ----
        const int rbase = m0 + wm + (lane >> 2);
        const int cbase = n0 + wn + (lane & 3) * 2;
#pragma unroll
        for (int mi = 0; mi < 2; ++mi)
#pragma unroll
            for (int nj = 0; nj < 4; ++nj) {
                const int r0 = rbase + mi * 16;
                const int c = cbase + nj * 8;
                if (r0 >= sLo && r0 < sHi) {
                    float2* p = (float2*)(Y + (size_t)r0 * ODIM + c);
                    float2 v = *p;
                    v.x += acc[mi][nj][0]; v.y += acc[mi][nj][1];
                    *p = v;
                }
                const int r1 = r0 + 8;
                if (r1 >= sLo && r1 < sHi) {
                    float2* p = (float2*)(Y + (size_t)r1 * ODIM + c);
                    float2 v = *p;
                    v.x += acc[mi][nj][2]; v.y += acc[mi][nj][3];
                    *p = v;
                }
            }
    }
}

extern "C" void kernel_launch(void* const* d_in, const int* in_sizes, int n_in,
                              void* d_out, int out_size) {
    const float* X   = (const float*)d_in[0];
    const int*   tpe = (const int*)d_in[1];
    const int*   Wq  = (const int*)d_in[2];
    const float* Sc  = (const float*)d_in[3];
    const float* Zr  = (const float*)d_in[4];
    float*       Y   = (float*)d_out;

    rowsum_k<<<NTOK / 4, 256>>>(X);
    dim3 gB(ODIM / 128, NTOK / 128);          // 22 x 16
    yinit_k<<<gB, 256>>>(tpe, Sc, Zr, Y);
    dim3 gM(ODIM / BN, NTOK / BM);            // 44 x 16
    hqq_main<<<gM, 256>>>(X, tpe, Wq, Sc, Y);
}

// round 7
// speedup vs baseline: 2.0035x; 1.1606x over previous
#include <cuda_runtime.h>
#include <cuda_fp16.h>
#include <cstdint>

// HQQ grouped GEMM: single-pass fp16 mma.sync with deferred group scales.
// y = sum_g s_g*(x~.q)_g - sum_g s_g*z_g*T_g,  T = per-group rowsums of fp16(x).
// Error = sum s*(x~-x)*(q-z) ~ 3e-4 rel (threshold 1e-3).
// E=8, K=1024, OUT=2816, GS=64, N=2048.
#define NE 8
#define KDIM 1024
#define ODIM 2816
#define NTOK 2048
#define GD 16           // KDIM/64 quant groups

#define BM 128
#define BN 64
#define BK 32
#define NKT (KDIM / BK) // 32

static __device__ float T_buf[NTOK * GD];

// fp32 -> fp16 -> fp32 round trip (inline PTX; avoids header dependence issues)
__device__ __forceinline__ float h_round(float f) {
    float r;
    asm("{ .reg .f16 t; cvt.rn.f16.f32 t, %1; cvt.f32.f16 %0, t; }"
        : "=f"(r) : "f"(f));
    return r;
}

// ---------------- kernel A: per-group rowsums of fp16-rounded x ----------------
__global__ void __launch_bounds__(256) rowsum_k(const float* __restrict__ X) {
    const int row = blockIdx.x * 4 + (threadIdx.x >> 6);
    const int p = threadIdx.x & 63;
    const float4* xp = (const float4*)(X + (size_t)row * KDIM + p * 16);
    float s = 0.f;
#pragma unroll
    for (int i = 0; i < 4; ++i) {
        float4 v = xp[i];
        // round through fp16 so the correction matches the MMA operand
        s += h_round(v.x) + h_round(v.y) + h_round(v.z) + h_round(v.w);
    }
    s += __shfl_xor_sync(0xffffffffu, s, 1);
    s += __shfl_xor_sync(0xffffffffu, s, 2);
    const int lane = threadIdx.x & 31;
    if ((lane & 3) == 0)
        T_buf[row * GD + ((threadIdx.x >> 5) & 1) * 8 + (lane >> 2)] = s;
}

// ---------------- kernel B: Y = - sum_g (s*z)[g,o] * T[n,g] ----------------
__global__ void __launch_bounds__(256) yinit_k(const int* __restrict__ tpe,
                                               const float* __restrict__ Sc,
                                               const float* __restrict__ Zr,
                                               float* __restrict__ Y) {
    __shared__ float Ts[128 * GD];
    const int tid = threadIdx.x;
    const int n0 = blockIdx.x * 128;
    const int m0 = blockIdx.y * 128;
    *(float4*)&Ts[tid * 8]     = *(const float4*)&T_buf[m0 * GD + tid * 8];
    *(float4*)&Ts[tid * 8 + 4] = *(const float4*)&T_buf[m0 * GD + tid * 8 + 4];
    __syncthreads();
    const int c0 = (tid & 31) * 4;
    const int rb = (tid >> 5) * 16;
    int cum = 0;
    for (int e = 0; e < NE; ++e) {
        const int lo = cum; cum += tpe[e];
        const int sLo = max(lo, m0), sHi = min(cum, m0 + 128);
        if (sLo >= sHi) continue;
        const float* Sp = Sc + (size_t)e * GD * ODIM + n0 + c0;
        const float* Zp = Zr + (size_t)e * GD * ODIM + n0 + c0;
        float y[16][4];
#pragma unroll
        for (int i = 0; i < 16; ++i) y[i][0] = y[i][1] = y[i][2] = y[i][3] = 0.f;
#pragma unroll
        for (int g = 0; g < GD; ++g) {
            const float4 s4 = *(const float4*)(Sp + (size_t)g * ODIM);
            const float4 z4 = *(const float4*)(Zp + (size_t)g * ODIM);
            const float4 u = make_float4(s4.x * z4.x, s4.y * z4.y,
                                         s4.z * z4.z, s4.w * z4.w);
#pragma unroll
            for (int i = 0; i < 16; ++i) {
                const float tv = Ts[(rb + i) * GD + g];
                y[i][0] -= u.x * tv; y[i][1] -= u.y * tv;
                y[i][2] -= u.z * tv; y[i][3] -= u.w * tv;
            }
        }
#pragma unroll
        for (int i = 0; i < 16; ++i) {
            const int r = m0 + rb + i;
            if (r >= sLo && r < sHi)
                *(float4*)(Y + (size_t)r * ODIM + n0 + c0) = *(float4*)y[i];
        }
    }
}

// ---------------- main kernel ----------------
__device__ __forceinline__ uint32_t cvt2h(float f0, float f1) {
    uint32_t r;
    asm("cvt.rn.f16x2.f32 %0, %1, %2;" : "=r"(r) : "f"(f1), "f"(f0)); // lo = f0
    return r;
}
__device__ __forceinline__ uint32_t cvt2hq(int a, int b) {
    uint32_t r;
    asm("cvt.rn.f16x2.f32 %0, %1, %2;" : "=r"(r) : "f"((float)b), "f"((float)a));
    return r;
}

#define LDSM4(r, a) asm volatile( \
    "ldmatrix.sync.aligned.m8n8.x4.shared.b16 {%0,%1,%2,%3}, [%4];" \
    : "=r"((r)[0]), "=r"((r)[1]), "=r"((r)[2]), "=r"((r)[3]) : "r"(a))
#define LDSM4T(r, a) asm volatile( \
    "ldmatrix.sync.aligned.m8n8.x4.trans.shared.b16 {%0,%1,%2,%3}, [%4];" \
    : "=r"((r)[0]), "=r"((r)[1]), "=r"((r)[2]), "=r"((r)[3]) : "r"(a))
#define MMAH(d, a, b0, b1) asm volatile( \
    "mma.sync.aligned.m16n8k16.row.col.f32.f16.f16.f32 " \
    "{%0,%1,%2,%3}, {%4,%5,%6,%7}, {%8,%9}, {%0,%1,%2,%3};" \
    : "+f"((d)[0]), "+f"((d)[1]), "+f"((d)[2]), "+f"((d)[3]) \
    : "r"((a)[0]), "r"((a)[1]), "r"((a)[2]), "r"((a)[3]), "r"(b0), "r"(b1))
#define MMAH_Z(d, a, b0, b1) asm volatile( \
    "mma.sync.aligned.m16n8k16.row.col.f32.f16.f16.f32 " \
    "{%0,%1,%2,%3}, {%4,%5,%6,%7}, {%8,%9}, {%10,%10,%10,%10};" \
    : "=f"((d)[0]), "=f"((d)[1]), "=f"((d)[2]), "=f"((d)[3]) \
    : "r"((a)[0]), "r"((a)[1]), "r"((a)[2]), "r"((a)[3]), "r"(b0), "r"(b1), \
      "f"(0.0f))

// smem layouts (chunk = 16B = 8 fp16):
//  X: 128 rows x 32 k, pitch 64B (4 chunks), swizzle c' = c ^ ((row>>1)&3)
//  W: 32 rows x 64 n, pitch 128B (8 chunks), swizzle c' = c ^ (row&7)
#define XBUF (BM * BK)
#define WBUF (BK * BN)

__global__ void __launch_bounds__(256, 2)
hqq_main(const float* __restrict__ X, const int* __restrict__ tpe,
         const int* __restrict__ Wq, const float* __restrict__ Sc,
         float* __restrict__ Y)
{
    __shared__ __align__(16) uint16_t XtS[2][XBUF];
    __shared__ __align__(16) uint16_t WtS[2][WBUF];

    const int tid = threadIdx.x;
    const int lane = tid & 31;
    const int wid = tid >> 5;
    const int wm = (wid & 3) * 32;
    const int wn = (wid >> 2) * 32;
    const int n0 = blockIdx.x * BN;
    const int m0 = blockIdx.y * BM;

    const uint32_t XtB = (uint32_t)__cvta_generic_to_shared(XtS);
    const uint32_t WtB = (uint32_t)__cvta_generic_to_shared(WtS);

    uint32_t aoff[2][2], boff[2][2];
#pragma unroll
    for (int mi = 0; mi < 2; ++mi)
#pragma unroll
        for (int s = 0; s < 2; ++s) {
            const int r = wm + mi * 16 + (lane & 15);
            const int c = s * 2 + (lane >> 4);
            aoff[mi][s] = (uint32_t)(r * 64 + ((c ^ ((r >> 1) & 3)) << 4));
        }
#pragma unroll
    for (int s = 0; s < 2; ++s)
#pragma unroll
        for (int nb = 0; nb < 2; ++nb) {
            const int r = s * 16 + (lane & 15);
            const int c = (wn >> 3) + nb * 2 + (lane >> 4);
            boff[s][nb] = (uint32_t)(r * 128 + ((c ^ (r & 7)) << 4));
        }

    // loader maps
    const int xrow = tid >> 1;
    const int xkc = (tid & 1) * 2;
    const float* Xp = X + (size_t)(m0 + xrow) * KDIM + (tid & 1) * 16;
    const uint32_t xsw0 = (uint32_t)(xrow * 64 + (((xkc + 0) ^ ((xrow >> 1) & 3)) << 4));
    const uint32_t xsw1 = (uint32_t)(xrow * 64 + (((xkc + 1) ^ ((xrow >> 1) & 3)) << 4));
    const int wrow = tid >> 3;
    const int wch = tid & 7;
    const uint32_t wsw = (uint32_t)(wrow * 128 + ((wch ^ (wrow & 7)) << 4));

    int cum = 0;
    for (int e = 0; e < NE; ++e) {
        const int lo = cum;
        cum += tpe[e];
        const int sLo = max(lo, m0), sHi = min(cum, m0 + BM);
        if (sLo >= sHi) continue;

        const int* Wb = Wq + (size_t)e * KDIM * ODIM + n0;
        const float* Sb = Sc + (size_t)e * GD * ODIM + n0;

        float acc[2][4][4];
#pragma unroll
        for (int i = 0; i < 2; ++i)
#pragma unroll
            for (int j = 0; j < 4; ++j)
#pragma unroll
                for (int r = 0; r < 4; ++r) acc[i][j][r] = 0.f;

        // ---- stage tile 0 ----
        float4 xs[4];
        int4 wv0, wv1;
#pragma unroll
        for (int j = 0; j < 4; ++j) xs[j] = *(const float4*)(Xp + j * 4);
        wv0 = *(const int4*)(Wb + (size_t)wrow * ODIM + wch * 8);
        wv1 = *(const int4*)(Wb + (size_t)wrow * ODIM + wch * 8 + 4);

        {
            uint32_t h0 = cvt2h(xs[0].x, xs[0].y), h1 = cvt2h(xs[0].z, xs[0].w);
            uint32_t h2 = cvt2h(xs[1].x, xs[1].y), h3 = cvt2h(xs[1].z, xs[1].w);
            uint32_t h4 = cvt2h(xs[2].x, xs[2].y), h5 = cvt2h(xs[2].z, xs[2].w);
            uint32_t h6 = cvt2h(xs[3].x, xs[3].y), h7 = cvt2h(xs[3].z, xs[3].w);
            asm volatile("st.shared.v4.b32 [%0], {%1,%2,%3,%4};" ::
                         "r"(XtB + xsw0), "r"(h0), "r"(h1), "r"(h2), "r"(h3));
            asm volatile("st.shared.v4.b32 [%0], {%1,%2,%3,%4};" ::
                         "r"(XtB + xsw1), "r"(h4), "r"(h5), "r"(h6), "r"(h7));
            uint32_t q0 = cvt2hq(wv0.x, wv0.y), q1 = cvt2hq(wv0.z, wv0.w);
            uint32_t q2 = cvt2hq(wv1.x, wv1.y), q3 = cvt2hq(wv1.z, wv1.w);
            asm volatile("st.shared.v4.b32 [%0], {%1,%2,%3,%4};" ::
                         "r"(WtB + wsw), "r"(q0), "r"(q1), "r"(q2), "r"(q3));
        }
        __syncthreads();

        float2 s2[4];
        for (int t = 0; t < NKT; ++t) {
            const int bb = t & 1;
            const uint32_t XtBb = XtB + bb * (XBUF * 2);
            const uint32_t WtBb = WtB + bb * (WBUF * 2);

            // issue global loads for tile t+1 (consumed after the MMA block)
            if (t + 1 < NKT) {
                const int kb = (t + 1) * BK;
#pragma unroll
                for (int j = 0; j < 4; ++j) xs[j] = *(const float4*)(Xp + kb + j * 4);
                wv0 = *(const int4*)(Wb + (size_t)(kb + wrow) * ODIM + wch * 8);
                wv1 = *(const int4*)(Wb + (size_t)(kb + wrow) * ODIM + wch * 8 + 4);
            }
            if ((t & 1) == 0) {
                const int g = t >> 1;
#pragma unroll
                for (int nj = 0; nj < 4; ++nj)
                    s2[nj] = *(const float2*)(Sb + (size_t)g * ODIM + wn + nj * 8 +
                                              (lane & 3) * 2);
            }

            // ---- MMA: 2 k-steps, single fp16 pass ----
            float tacc[2][4][4];
#pragma unroll
            for (int s = 0; s < 2; ++s) {
                uint32_t Av[2][4], Bv[2][4];
                LDSM4(Av[0], XtBb + aoff[0][s]);
                LDSM4(Av[1], XtBb + aoff[1][s]);
                LDSM4T(Bv[0], WtBb + boff[s][0]);
                LDSM4T(Bv[1], WtBb + boff[s][1]);
#pragma unroll
                for (int mi = 0; mi < 2; ++mi)
#pragma unroll
                    for (int nj = 0; nj < 4; ++nj) {
                        const uint32_t b0 = Bv[nj >> 1][(nj & 1) * 2];
                        const uint32_t b1 = Bv[nj >> 1][(nj & 1) * 2 + 1];
                        if (s == 0) { MMAH_Z(tacc[mi][nj], Av[mi], b0, b1); }
                        else        { MMAH(tacc[mi][nj], Av[mi], b0, b1); }
                    }
            }
            // fold group scale: acc += s * tacc
#pragma unroll
            for (int mi = 0; mi < 2; ++mi)
#pragma unroll
                for (int nj = 0; nj < 4; ++nj) {
                    acc[mi][nj][0] += s2[nj].x * tacc[mi][nj][0];
                    acc[mi][nj][1] += s2[nj].y * tacc[mi][nj][1];
                    acc[mi][nj][2] += s2[nj].x * tacc[mi][nj][2];
                    acc[mi][nj][3] += s2[nj].y * tacc[mi][nj][3];
                }

            // store tile t+1 into the other buffer
            if (t + 1 < NKT) {
                const uint32_t Xt2 = XtB + (1 - bb) * (XBUF * 2);
                const uint32_t Wt2 = WtB + (1 - bb) * (WBUF * 2);
                uint32_t h0 = cvt2h(xs[0].x, xs[0].y), h1 = cvt2h(xs[0].z, xs[0].w);
                uint32_t h2 = cvt2h(xs[1].x, xs[1].y), h3 = cvt2h(xs[1].z, xs[1].w);
                uint32_t h4 = cvt2h(xs[2].x, xs[2].y), h5 = cvt2h(xs[2].z, xs[2].w);
                uint32_t h6 = cvt2h(xs[3].x, xs[3].y), h7 = cvt2h(xs[3].z, xs[3].w);
                asm volatile("st.shared.v4.b32 [%0], {%1,%2,%3,%4};" ::
                             "r"(Xt2 + xsw0), "r"(h0), "r"(h1), "r"(h2), "r"(h3));
                asm volatile("st.shared.v4.b32 [%0], {%1,%2,%3,%4};" ::
                             "r"(Xt2 + xsw1), "r"(h4), "r"(h5), "r"(h6), "r"(h7));
                uint32_t q0 = cvt2hq(wv0.x, wv0.y), q1 = cvt2hq(wv0.z, wv0.w);
                uint32_t q2 = cvt2hq(wv1.x, wv1.y), q3 = cvt2hq(wv1.z, wv1.w);
                asm volatile("st.shared.v4.b32 [%0], {%1,%2,%3,%4};" ::
                             "r"(Wt2 + wsw), "r"(q0), "r"(q1), "r"(q2), "r"(q3));
            }
            __syncthreads();
        }

        // ---- epilogue: Y += acc on this expert's rows ----
        const int rbase = m0 + wm + (lane >> 2);
        const int cbase = n0 + wn + (lane & 3) * 2;
#pragma unroll
        for (int mi = 0; mi < 2; ++mi)
#pragma unroll
            for (int nj = 0; nj < 4; ++nj) {
                const int r0 = rbase + mi * 16;
                const int c = cbase + nj * 8;
                if (r0 >= sLo && r0 < sHi) {
                    float2* p = (float2*)(Y + (size_t)r0 * ODIM + c);
                    float2 v = *p;
                    v.x += acc[mi][nj][0]; v.y += acc[mi][nj][1];
                    *p = v;
                }
                const int r1 = r0 + 8;
                if (r1 >= sLo && r1 < sHi) {
                    float2* p = (float2*)(Y + (size_t)r1 * ODIM + c);
                    float2 v = *p;
                    v.x += acc[mi][nj][2]; v.y += acc[mi][nj][3];
                    *p = v;
                }
            }
    }
}

extern "C" void kernel_launch(void* const* d_in, const int* in_sizes, int n_in,
                              void* d_out, int out_size) {
    const float* X   = (const float*)d_in[0];
    const int*   tpe = (const int*)d_in[1];
    const int*   Wq  = (const int*)d_in[2];
    const float* Sc  = (const float*)d_in[3];
    const float* Zr  = (const float*)d_in[4];
    float*       Y   = (float*)d_out;

    rowsum_k<<<NTOK / 4, 256>>>(X);
    dim3 gB(ODIM / 128, NTOK / 128);
    yinit_k<<<gB, 256>>>(tpe, Sc, Zr, Y);
    dim3 gM(ODIM / BN, NTOK / BM);
    hqq_main<<<gM, 256>>>(X, tpe, Wq, Sc, Y);
}

// round 8
// speedup vs baseline: 2.7479x; 1.3715x over previous
#include <cuda_runtime.h>
#include <cstdint>

// HQQ grouped GEMM: fp16 single-pass mma.sync, cp.async 4-stage pipeline,
// conversions hoisted to pre-pass kernels.
// y = sum_g s_g*(x~.q)_g - sum_g s_g*z_g*T_g,  T = per-group rowsums of fp16(x).
// E=8, K=1024, OUT=2816, GS=64, N=2048.
#define NE 8
#define KDIM 1024
#define ODIM 2816
#define NTOK 2048
#define GD 16           // KDIM/64 quant groups

#define BM 128
#define BN 64
#define BK 32
#define NKT (KDIM / BK) // 32
#define STAGES 4

static __device__ float    T_buf[NTOK * GD];
static __device__ uint16_t Xh_buf[NTOK * KDIM];                       // 4 MB
static __device__ uint16_t Wh_buf[(size_t)NE * KDIM * ODIM];          // 46 MB

__device__ __forceinline__ float h_round(float f) {
    float r;
    asm("{ .reg .f16 t; cvt.rn.f16.f32 t, %1; cvt.f32.f16 %0, t; }"
        : "=f"(r) : "f"(f));
    return r;
}
__device__ __forceinline__ uint32_t cvt2h(float f0, float f1) {
    uint32_t r;
    asm("cvt.rn.f16x2.f32 %0, %1, %2;" : "=r"(r) : "f"(f1), "f"(f0)); // lo = f0
    return r;
}
__device__ __forceinline__ uint32_t cvt2hq(int a, int b) {
    uint32_t r;
    asm("cvt.rn.f16x2.f32 %0, %1, %2;" : "=r"(r) : "f"((float)b), "f"((float)a));
    return r;
}

// ---------------- pre-pass: X -> fp16 scratch + fused group rowsums ----------------
__global__ void __launch_bounds__(256) xcvt_k(const float* __restrict__ X) {
    const int row = blockIdx.x;
    const int t = threadIdx.x;
    const float4 v = *(const float4*)(X + (size_t)row * KDIM + t * 4);
    uint32_t h0 = cvt2h(v.x, v.y), h1 = cvt2h(v.z, v.w);
    *(uint2*)(Xh_buf + (size_t)row * KDIM + t * 4) = make_uint2(h0, h1);
    float s = h_round(v.x) + h_round(v.y) + h_round(v.z) + h_round(v.w);
    s += __shfl_xor_sync(0xffffffffu, s, 1);
    s += __shfl_xor_sync(0xffffffffu, s, 2);
    s += __shfl_xor_sync(0xffffffffu, s, 4);
    s += __shfl_xor_sync(0xffffffffu, s, 8);
    if ((t & 15) == 0) T_buf[row * GD + (t >> 4)] = s;
}

// ---------------- pre-pass: W_q int32 -> fp16 scratch ----------------
__global__ void __launch_bounds__(256) wcvt_k(const int* __restrict__ Wq) {
    const size_t i = ((size_t)blockIdx.x * 256 + threadIdx.x) * 8;
    const int4 a = *(const int4*)(Wq + i);
    const int4 b = *(const int4*)(Wq + i + 4);
    uint4 o;
    o.x = cvt2hq(a.x, a.y); o.y = cvt2hq(a.z, a.w);
    o.z = cvt2hq(b.x, b.y); o.w = cvt2hq(b.z, b.w);
    *(uint4*)(Wh_buf + i) = o;
}

// ---------------- kernel: Y = - sum_g (s*z)[g,o] * T[n,g] ----------------
__global__ void __launch_bounds__(256) yinit_k(const int* __restrict__ tpe,
                                               const float* __restrict__ Sc,
                                               const float* __restrict__ Zr,
                                               float* __restrict__ Y) {
    __shared__ float Ts[128 * GD];
    const int tid = threadIdx.x;
    const int n0 = blockIdx.x * 128;
    const int m0 = blockIdx.y * 128;
    *(float4*)&Ts[tid * 8]     = *(const float4*)&T_buf[m0 * GD + tid * 8];
    *(float4*)&Ts[tid * 8 + 4] = *(const float4*)&T_buf[m0 * GD + tid * 8 + 4];
    __syncthreads();
    const int c0 = (tid & 31) * 4;
    const int rb = (tid >> 5) * 16;
    int cum = 0;
    for (int e = 0; e < NE; ++e) {
        const int lo = cum; cum += tpe[e];
        const int sLo = max(lo, m0), sHi = min(cum, m0 + 128);
        if (sLo >= sHi) continue;
        const float* Sp = Sc + (size_t)e * GD * ODIM + n0 + c0;
        const float* Zp = Zr + (size_t)e * GD * ODIM + n0 + c0;
        float y[16][4];
#pragma unroll
        for (int i = 0; i < 16; ++i) y[i][0] = y[i][1] = y[i][2] = y[i][3] = 0.f;
#pragma unroll
        for (int g = 0; g < GD; ++g) {
            const float4 s4 = *(const float4*)(Sp + (size_t)g * ODIM);
            const float4 z4 = *(const float4*)(Zp + (size_t)g * ODIM);
            const float4 u = make_float4(s4.x * z4.x, s4.y * z4.y,
                                         s4.z * z4.z, s4.w * z4.w);
#pragma unroll
            for (int i = 0; i < 16; ++i) {
                const float tv = Ts[(rb + i) * GD + g];
                y[i][0] -= u.x * tv; y[i][1] -= u.y * tv;
                y[i][2] -= u.z * tv; y[i][3] -= u.w * tv;
            }
        }
#pragma unroll
        for (int i = 0; i < 16; ++i) {
            const int r = m0 + rb + i;
            if (r >= sLo && r < sHi)
                *(float4*)(Y + (size_t)r * ODIM + n0 + c0) = *(float4*)y[i];
        }
    }
}

// ---------------- main kernel ----------------
#define LDSM4(r, a) asm volatile( \
    "ldmatrix.sync.aligned.m8n8.x4.shared.b16 {%0,%1,%2,%3}, [%4];" \
    : "=r"((r)[0]), "=r"((r)[1]), "=r"((r)[2]), "=r"((r)[3]) : "r"(a))
#define LDSM4T(r, a) asm volatile( \
    "ldmatrix.sync.aligned.m8n8.x4.trans.shared.b16 {%0,%1,%2,%3}, [%4];" \
    : "=r"((r)[0]), "=r"((r)[1]), "=r"((r)[2]), "=r"((r)[3]) : "r"(a))
#define MMAH(d, a, b0, b1) asm volatile( \
    "mma.sync.aligned.m16n8k16.row.col.f32.f16.f16.f32 " \
    "{%0,%1,%2,%3}, {%4,%5,%6,%7}, {%8,%9}, {%0,%1,%2,%3};" \
    : "+f"((d)[0]), "+f"((d)[1]), "+f"((d)[2]), "+f"((d)[3]) \
    : "r"((a)[0]), "r"((a)[1]), "r"((a)[2]), "r"((a)[3]), "r"(b0), "r"(b1))
#define MMAH_Z(d, a, b0, b1) asm volatile( \
    "mma.sync.aligned.m16n8k16.row.col.f32.f16.f16.f32 " \
    "{%0,%1,%2,%3}, {%4,%5,%6,%7}, {%8,%9}, {%10,%10,%10,%10};" \
    : "=f"((d)[0]), "=f"((d)[1]), "=f"((d)[2]), "=f"((d)[3]) \
    : "r"((a)[0]), "r"((a)[1]), "r"((a)[2]), "r"((a)[3]), "r"(b0), "r"(b1), \
      "f"(0.0f))
#define CPA(dst, src) asm volatile( \
    "cp.async.cg.shared.global [%0], [%1], 16;" :: "r"(dst), "l"(src))
#define CPA_COMMIT() asm volatile("cp.async.commit_group;" ::: "memory")
#define CPA_WAIT2() asm volatile("cp.async.wait_group 2;" ::: "memory")
#define CPA_WAIT0() asm volatile("cp.async.wait_group 0;" ::: "memory")

// smem layouts (chunk = 16B = 8 fp16):
//  X stage: 128 rows x 32 k, pitch 64B (4 chunks), swizzle c' = c ^ ((row>>1)&3)
//  W stage: 32 rows x 64 n, pitch 128B (8 chunks), swizzle c' = c ^ (row&7)
#define XBYTES (BM * BK * 2)   // 8192
#define WBYTES (BK * BN * 2)   // 4096

__global__ void __launch_bounds__(256, 2)
hqq_main(const int* __restrict__ tpe, const float* __restrict__ Sc,
         float* __restrict__ Y)
{
    __shared__ __align__(16) uint16_t XS[STAGES][BM * BK];
    __shared__ __align__(16) uint16_t WS[STAGES][BK * BN];

    const int tid = threadIdx.x;
    const int lane = tid & 31;
    const int wid = tid >> 5;
    const int wm = (wid & 3) * 32;
    const int wn = (wid >> 2) * 32;
    const int n0 = blockIdx.x * BN;
    const int m0 = blockIdx.y * BM;

    const uint32_t XtB = (uint32_t)__cvta_generic_to_shared(XS);
    const uint32_t WtB = (uint32_t)__cvta_generic_to_shared(WS);

    // ldmatrix byte offsets (stage-relative)
    uint32_t aoff[2][2], boff[2][2];
#pragma unroll
    for (int mi = 0; mi < 2; ++mi)
#pragma unroll
        for (int s = 0; s < 2; ++s) {
            const int r = wm + mi * 16 + (lane & 15);
            const int c = s * 2 + (lane >> 4);
            aoff[mi][s] = (uint32_t)(r * 64 + ((c ^ ((r >> 1) & 3)) << 4));
        }
#pragma unroll
    for (int s = 0; s < 2; ++s)
#pragma unroll
        for (int nb = 0; nb < 2; ++nb) {
            const int r = s * 16 + (lane & 15);
            const int c = (wn >> 3) + nb * 2 + (lane >> 4);
            boff[s][nb] = (uint32_t)(r * 128 + ((c ^ (r & 7)) << 4));
        }

    // cp.async per-thread maps
    const int xr = tid >> 1;
    const int xc0 = (tid & 1) * 2;            // chunk base 0 or 2
    const uint16_t* xsrc = Xh_buf + (size_t)(m0 + xr) * KDIM + (tid & 1) * 16;
    const uint32_t xd0 = (uint32_t)(xr * 64 + (((xc0 + 0) ^ ((xr >> 1) & 3)) << 4));
    const uint32_t xd1 = (uint32_t)(xr * 64 + (((xc0 + 1) ^ ((xr >> 1) & 3)) << 4));
    const int wr = tid >> 3;
    const int wc = tid & 7;
    const uint32_t wd = (uint32_t)(wr * 128 + ((wc ^ (wr & 7)) << 4));

    int cum = 0;
    for (int e = 0; e < NE; ++e) {
        const int lo = cum;
        cum += tpe[e];
        const int sLo = max(lo, m0), sHi = min(cum, m0 + BM);
        if (sLo >= sHi) continue;

        const uint16_t* wsrc = Wh_buf + (size_t)e * KDIM * ODIM +
                               (size_t)wr * ODIM + n0 + wc * 8;
        const float* Sb = Sc + (size_t)e * GD * ODIM + n0;

        float acc[2][4][4];
#pragma unroll
        for (int i = 0; i < 2; ++i)
#pragma unroll
            for (int j = 0; j < 4; ++j)
#pragma unroll
                for (int r = 0; r < 4; ++r) acc[i][j][r] = 0.f;

        // ---- prologue: issue tiles 0..2 ----
#pragma unroll
        for (int p = 0; p < STAGES - 1; ++p) {
            CPA(XtB + p * XBYTES + xd0, xsrc + p * BK);
            CPA(XtB + p * XBYTES + xd1, xsrc + p * BK + 8);
            CPA(WtB + p * WBYTES + wd, wsrc + (size_t)p * BK * ODIM);
            CPA_COMMIT();
        }

        float2 s2[4];
        float tacc[2][4][4];
        for (int t = 0; t < NKT; ++t) {
            CPA_WAIT2();
            __syncthreads();

            // issue tile t+3 into slot (t+3)%4; always commit (empty ok)
            if (t + STAGES - 1 < NKT) {
                const int sl = (t + STAGES - 1) & (STAGES - 1);
                const int kb = (t + STAGES - 1) * BK;
                CPA(XtB + sl * XBYTES + xd0, xsrc + kb);
                CPA(XtB + sl * XBYTES + xd1, xsrc + kb + 8);
                CPA(WtB + sl * WBYTES + wd, wsrc + (size_t)kb * ODIM);
            }
            CPA_COMMIT();

            if ((t & 1) == 0) {
                const int g = t >> 1;
#pragma unroll
                for (int nj = 0; nj < 4; ++nj)
                    s2[nj] = *(const float2*)(Sb + (size_t)g * ODIM + wn + nj * 8 +
                                              (lane & 3) * 2);
            }

            const uint32_t XtBb = XtB + (t & (STAGES - 1)) * XBYTES;
            const uint32_t WtBb = WtB + (t & (STAGES - 1)) * WBYTES;

            // ---- 2 k-steps of fp16 MMA ----
#pragma unroll
            for (int s = 0; s < 2; ++s) {
                uint32_t Av[2][4], Bv[2][4];
                LDSM4(Av[0], XtBb + aoff[0][s]);
                LDSM4(Av[1], XtBb + aoff[1][s]);
                LDSM4T(Bv[0], WtBb + boff[s][0]);
                LDSM4T(Bv[1], WtBb + boff[s][1]);
#pragma unroll
                for (int mi = 0; mi < 2; ++mi)
#pragma unroll
                    for (int nj = 0; nj < 4; ++nj) {
                        const uint32_t b0 = Bv[nj >> 1][(nj & 1) * 2];
                        const uint32_t b1 = Bv[nj >> 1][(nj & 1) * 2 + 1];
                        if ((t & 1) == 0 && s == 0) {
                            MMAH_Z(tacc[mi][nj], Av[mi], b0, b1);
                        } else {
                            MMAH(tacc[mi][nj], Av[mi], b0, b1);
                        }
                    }
            }
            // fold group scale once per 2 tiles (group = 64 k = 2 tiles)
            if (t & 1) {
#pragma unroll
                for (int mi = 0; mi < 2; ++mi)
#pragma unroll
                    for (int nj = 0; nj < 4; ++nj) {
                        acc[mi][nj][0] += s2[nj].x * tacc[mi][nj][0];
                        acc[mi][nj][1] += s2[nj].y * tacc[mi][nj][1];
                        acc[mi][nj][2] += s2[nj].x * tacc[mi][nj][2];
                        acc[mi][nj][3] += s2[nj].y * tacc[mi][nj][3];
                    }
            }
        }
        CPA_WAIT0();
        __syncthreads();

        // ---- epilogue: Y += acc on this expert's rows ----
        const int rbase = m0 + wm + (lane >> 2);
        const int cbase = n0 + wn + (lane & 3) * 2;
#pragma unroll
        for (int mi = 0; mi < 2; ++mi)
#pragma unroll
            for (int nj = 0; nj < 4; ++nj) {
                const int r0 = rbase + mi * 16;
                const int c = cbase + nj * 8;
                if (r0 >= sLo && r0 < sHi) {
                    float2* p = (float2*)(Y + (size_t)r0 * ODIM + c);
                    float2 v = *p;
                    v.x += acc[mi][nj][0]; v.y += acc[mi][nj][1];
                    *p = v;
                }
                const int r1 = r0 + 8;
                if (r1 >= sLo && r1 < sHi) {
                    float2* p = (float2*)(Y + (size_t)r1 * ODIM + c);
                    float2 v = *p;
                    v.x += acc[mi][nj][2]; v.y += acc[mi][nj][3];
                    *p = v;
                }
            }
        __syncthreads();
    }
}

extern "C" void kernel_launch(void* const* d_in, const int* in_sizes, int n_in,
                              void* d_out, int out_size) {
    const float* X   = (const float*)d_in[0];
    const int*   tpe = (const int*)d_in[1];
    const int*   Wq  = (const int*)d_in[2];
    const float* Sc  = (const float*)d_in[3];
    const float* Zr  = (const float*)d_in[4];
    float*       Y   = (float*)d_out;

    xcvt_k<<<NTOK, 256>>>(X);
    wcvt_k<<<(NE * KDIM * ODIM) / (256 * 8), 256>>>(Wq);   // 11264 blocks
    dim3 gB(ODIM / 128, NTOK / 128);
    yinit_k<<<gB, 256>>>(tpe, Sc, Zr, Y);
    dim3 gM(ODIM / BN, NTOK / BM);                         // 44 x 16
    hqq_main<<<gM, 256>>>(tpe, Sc, Y);
}

// round 9
// speedup vs baseline: 3.2107x; 1.1684x over previous
#include <cuda_runtime.h>
#include <cstdint>

// HQQ grouped GEMM: plain fp16 mma.sync pipeline over pre-scaled weights.
// Wh = fp16(s * q); y = x~ . Wh - sum_g s_g*z_g*T_g (exact fp32 correction).
// E=8, K=1024, OUT=2816, GS=64, N=2048.
#define NE 8
#define KDIM 1024
#define ODIM 2816
#define NTOK 2048
#define GD 16           // KDIM/64 quant groups

#define BM 128
#define BN 64
#define BK 32
#define NKT (KDIM / BK) // 32
#define STAGES 4

static __device__ float    T_buf[NTOK * GD];
static __device__ uint16_t Xh_buf[NTOK * KDIM];                       // 4 MB
static __device__ uint16_t Wh_buf[(size_t)NE * KDIM * ODIM];          // 46 MB

__device__ __forceinline__ float h_round(float f) {
    float r;
    asm("{ .reg .f16 t; cvt.rn.f16.f32 t, %1; cvt.f32.f16 %0, t; }"
        : "=f"(r) : "f"(f));
    return r;
}
__device__ __forceinline__ uint32_t cvt2h(float f0, float f1) {
    uint32_t r;
    asm("cvt.rn.f16x2.f32 %0, %1, %2;" : "=r"(r) : "f"(f1), "f"(f0)); // lo = f0
    return r;
}

// ---------------- pre-pass: X -> fp16 scratch + fused group rowsums ----------------
__global__ void __launch_bounds__(256) xcvt_k(const float* __restrict__ X) {
    const int row = blockIdx.x;
    const int t = threadIdx.x;
    const float4 v = *(const float4*)(X + (size_t)row * KDIM + t * 4);
    uint32_t h0 = cvt2h(v.x, v.y), h1 = cvt2h(v.z, v.w);
    *(uint2*)(Xh_buf + (size_t)row * KDIM + t * 4) = make_uint2(h0, h1);
    float s = h_round(v.x) + h_round(v.y) + h_round(v.z) + h_round(v.w);
    s += __shfl_xor_sync(0xffffffffu, s, 1);
    s += __shfl_xor_sync(0xffffffffu, s, 2);
    s += __shfl_xor_sync(0xffffffffu, s, 4);
    s += __shfl_xor_sync(0xffffffffu, s, 8);
    if ((t & 15) == 0) T_buf[row * GD + (t >> 4)] = s;
}

// ---------------- pre-pass: Wh = fp16(scale * q) ----------------
__global__ void __launch_bounds__(256) wcvt_k(const int* __restrict__ Wq,
                                              const float* __restrict__ Sc,
                                              const int* __restrict__ tpe) {
    const size_t i = ((size_t)blockIdx.x * 256 + threadIdx.x) * 8;
    const int e = (int)(i / ((size_t)KDIM * ODIM));
    if (tpe[e] == 0) return;   // expert has no tokens: its W is never read
    const size_t rem = i % ((size_t)KDIM * ODIM);
    const int k = (int)(rem / ODIM);
    const int o = (int)(rem % ODIM);
    const float* sp = Sc + ((size_t)e * GD + (k >> 6)) * ODIM + o;
    const float4 s0 = *(const float4*)sp;
    const float4 s1 = *(const float4*)(sp + 4);
    const int4 a = *(const int4*)(Wq + i);
    const int4 b = *(const int4*)(Wq + i + 4);
    uint4 oV;
    oV.x = cvt2h(s0.x * (float)a.x, s0.y * (float)a.y);
    oV.y = cvt2h(s0.z * (float)a.z, s0.w * (float)a.w);
    oV.z = cvt2h(s1.x * (float)b.x, s1.y * (float)b.y);
    oV.w = cvt2h(s1.z * (float)b.z, s1.w * (float)b.w);
    *(uint4*)(Wh_buf + i) = oV;
}

// ---------------- kernel: Y = - sum_g (s*z)[g,o] * T[n,g] ----------------
__global__ void __launch_bounds__(256) yinit_k(const int* __restrict__ tpe,
                                               const float* __restrict__ Sc,
                                               const float* __restrict__ Zr,
                                               float* __restrict__ Y) {
    __shared__ float Ts[128 * GD];
    const int tid = threadIdx.x;
    const int n0 = blockIdx.x * 128;
    const int m0 = blockIdx.y * 128;
    *(float4*)&Ts[tid * 8]     = *(const float4*)&T_buf[m0 * GD + tid * 8];
    *(float4*)&Ts[tid * 8 + 4] = *(const float4*)&T_buf[m0 * GD + tid * 8 + 4];
    __syncthreads();
    const int c0 = (tid & 31) * 4;
    const int rb = (tid >> 5) * 16;
    int cum = 0;
    for (int e = 0; e < NE; ++e) {
        const int lo = cum; cum += tpe[e];
        const int sLo = max(lo, m0), sHi = min(cum, m0 + 128);
        if (sLo >= sHi) continue;
        const float* Sp = Sc + (size_t)e * GD * ODIM + n0 + c0;
        const float* Zp = Zr + (size_t)e * GD * ODIM + n0 + c0;
        float y[16][4];
#pragma unroll
        for (int i = 0; i < 16; ++i) y[i][0] = y[i][1] = y[i][2] = y[i][3] = 0.f;
#pragma unroll
        for (int g = 0; g < GD; ++g) {
            const float4 s4 = *(const float4*)(Sp + (size_t)g * ODIM);
            const float4 z4 = *(const float4*)(Zp + (size_t)g * ODIM);
            const float4 u = make_float4(s4.x * z4.x, s4.y * z4.y,
                                         s4.z * z4.z, s4.w * z4.w);
#pragma unroll
            for (int i = 0; i < 16; ++i) {
                const float tv = Ts[(rb + i) * GD + g];
                y[i][0] -= u.x * tv; y[i][1] -= u.y * tv;
                y[i][2] -= u.z * tv; y[i][3] -= u.w * tv;
            }
        }
#pragma unroll
        for (int i = 0; i < 16; ++i) {
            const int r = m0 + rb + i;
            if (r >= sLo && r < sHi)
                *(float4*)(Y + (size_t)r * ODIM + n0 + c0) = *(float4*)y[i];
        }
    }
}

// ---------------- main kernel ----------------
#define LDSM4(r, a) asm volatile( \
    "ldmatrix.sync.aligned.m8n8.x4.shared.b16 {%0,%1,%2,%3}, [%4];" \
    : "=r"((r)[0]), "=r"((r)[1]), "=r"((r)[2]), "=r"((r)[3]) : "r"(a))
#define LDSM4T(r, a) asm volatile( \
    "ldmatrix.sync.aligned.m8n8.x4.trans.shared.b16 {%0,%1,%2,%3}, [%4];" \
    : "=r"((r)[0]), "=r"((r)[1]), "=r"((r)[2]), "=r"((r)[3]) : "r"(a))
#define MMAH(d, a, b0, b1) asm volatile( \
    "mma.sync.aligned.m16n8k16.row.col.f32.f16.f16.f32 " \
    "{%0,%1,%2,%3}, {%4,%5,%6,%7}, {%8,%9}, {%0,%1,%2,%3};" \
    : "+f"((d)[0]), "+f"((d)[1]), "+f"((d)[2]), "+f"((d)[3]) \
    : "r"((a)[0]), "r"((a)[1]), "r"((a)[2]), "r"((a)[3]), "r"(b0), "r"(b1))
#define MMAH_Z(d, a, b0, b1) asm volatile( \
    "mma.sync.aligned.m16n8k16.row.col.f32.f16.f16.f32 " \
    "{%0,%1,%2,%3}, {%4,%5,%6,%7}, {%8,%9}, {%10,%10,%10,%10};" \
    : "=f"((d)[0]), "=f"((d)[1]), "=f"((d)[2]), "=f"((d)[3]) \
    : "r"((a)[0]), "r"((a)[1]), "r"((a)[2]), "r"((a)[3]), "r"(b0), "r"(b1), \
      "f"(0.0f))
#define CPA(dst, src) asm volatile( \
    "cp.async.cg.shared.global [%0], [%1], 16;" :: "r"(dst), "l"(src))
#define CPA_COMMIT() asm volatile("cp.async.commit_group;" ::: "memory")
#define CPA_WAIT2() asm volatile("cp.async.wait_group 2;" ::: "memory")
#define CPA_WAIT0() asm volatile("cp.async.wait_group 0;" ::: "memory")

#define XBYTES (BM * BK * 2)   // 8192
#define WBYTES (BK * BN * 2)   // 4096

__global__ void __launch_bounds__(256, 3)
hqq_main(const int* __restrict__ tpe, float* __restrict__ Y)
{
    __shared__ __align__(16) uint16_t XS[STAGES][BM * BK];
    __shared__ __align__(16) uint16_t WS[STAGES][BK * BN];

    const int tid = threadIdx.x;
    const int lane = tid & 31;
    const int wid = tid >> 5;
    const int wm = (wid & 3) * 32;
    const int wn = (wid >> 2) * 32;
    const int n0 = blockIdx.x * BN;
    const int m0 = blockIdx.y * BM;

    const uint32_t XtB = (uint32_t)__cvta_generic_to_shared(XS);
    const uint32_t WtB = (uint32_t)__cvta_generic_to_shared(WS);

    uint32_t aoff[2][2], boff[2][2];
#pragma unroll
    for (int mi = 0; mi < 2; ++mi)
#pragma unroll
        for (int s = 0; s < 2; ++s) {
            const int r = wm + mi * 16 + (lane & 15);
            const int c = s * 2 + (lane >> 4);
            aoff[mi][s] = (uint32_t)(r * 64 + ((c ^ ((r >> 1) & 3)) << 4));
        }
#pragma unroll
    for (int s = 0; s < 2; ++s)
#pragma unroll
        for (int nb = 0; nb < 2; ++nb) {
            const int r = s * 16 + (lane & 15);
            const int c = (wn >> 3) + nb * 2 + (lane >> 4);
            boff[s][nb] = (uint32_t)(r * 128 + ((c ^ (r & 7)) << 4));
        }

    // cp.async per-thread maps
    const int xr = tid >> 1;
    const int xc0 = (tid & 1) * 2;
    const uint16_t* xsrc = Xh_buf + (size_t)(m0 + xr) * KDIM + (tid & 1) * 16;
    const uint32_t xd0 = (uint32_t)(xr * 64 + (((xc0 + 0) ^ ((xr >> 1) & 3)) << 4));
    const uint32_t xd1 = (uint32_t)(xr * 64 + (((xc0 + 1) ^ ((xr >> 1) & 3)) << 4));
    const int wr = tid >> 3;
    const int wc = tid & 7;
    const uint32_t wd = (uint32_t)(wr * 128 + ((wc ^ (wr & 7)) << 4));

    int cum = 0;
    for (int e = 0; e < NE; ++e) {
        const int lo = cum;
        cum += tpe[e];
        const int sLo = max(lo, m0), sHi = min(cum, m0 + BM);
        if (sLo >= sHi) continue;

        const uint16_t* wsrc = Wh_buf + (size_t)e * KDIM * ODIM +
                               (size_t)wr * ODIM + n0 + wc * 8;

        // ---- prologue: issue tiles 0..2 ----
#pragma unroll
        for (int p = 0; p < STAGES - 1; ++p) {
            CPA(XtB + p * XBYTES + xd0, xsrc + p * BK);
            CPA(XtB + p * XBYTES + xd1, xsrc + p * BK + 8);
            CPA(WtB + p * WBYTES + wd, wsrc + (size_t)p * BK * ODIM);
            CPA_COMMIT();
        }

        float acc[2][4][4];
        for (int t = 0; t < NKT; ++t) {
            CPA_WAIT2();
            __syncthreads();

            if (t + STAGES - 1 < NKT) {
                const int sl = (t + STAGES - 1) & (STAGES - 1);
                const int kb = (t + STAGES - 1) * BK;
                CPA(XtB + sl * XBYTES + xd0, xsrc + kb);
                CPA(XtB + sl * XBYTES + xd1, xsrc + kb + 8);
                CPA(WtB + sl * WBYTES + wd, wsrc + (size_t)kb * ODIM);
            }
            CPA_COMMIT();

            const uint32_t XtBb = XtB + (t & (STAGES - 1)) * XBYTES;
            const uint32_t WtBb = WtB + (t & (STAGES - 1)) * WBYTES;

#pragma unroll
            for (int s = 0; s < 2; ++s) {
                uint32_t Av[2][4], Bv[2][4];
                LDSM4(Av[0], XtBb + aoff[0][s]);
                LDSM4(Av[1], XtBb + aoff[1][s]);
                LDSM4T(Bv[0], WtBb + boff[s][0]);
                LDSM4T(Bv[1], WtBb + boff[s][1]);
#pragma unroll
                for (int mi = 0; mi < 2; ++mi)
#pragma unroll
                    for (int nj = 0; nj < 4; ++nj) {
                        const uint32_t b0 = Bv[nj >> 1][(nj & 1) * 2];
                        const uint32_t b1 = Bv[nj >> 1][(nj & 1) * 2 + 1];
                        if (t == 0 && s == 0) {
                            MMAH_Z(acc[mi][nj], Av[mi], b0, b1);
                        } else {
                            MMAH(acc[mi][nj], Av[mi], b0, b1);
                        }
                    }
            }
        }
        CPA_WAIT0();
        __syncthreads();

        // ---- epilogue: Y += acc on this expert's rows ----
        const int rbase = m0 + wm + (lane >> 2);
        const int cbase = n0 + wn + (lane & 3) * 2;
#pragma unroll
        for (int mi = 0; mi < 2; ++mi)
#pragma unroll
            for (int nj = 0; nj < 4; ++nj) {
                const int r0 = rbase + mi * 16;
                const int c = cbase + nj * 8;
                if (r0 >= sLo && r0 < sHi) {
                    float2* p = (float2*)(Y + (size_t)r0 * ODIM + c);
                    float2 v = *p;
                    v.x += acc[mi][nj][0]; v.y += acc[mi][nj][1];
                    *p = v;
                }
                const int r1 = r0 + 8;
                if (r1 >= sLo && r1 < sHi) {
                    float2* p = (float2*)(Y + (size_t)r1 * ODIM + c);
                    float2 v = *p;
                    v.x += acc[mi][nj][2]; v.y += acc[mi][nj][3];
                    *p = v;
                }
            }
        __syncthreads();
    }
}

extern "C" void kernel_launch(void* const* d_in, const int* in_sizes, int n_in,
                              void* d_out, int out_size) {
    const float* X   = (const float*)d_in[0];
    const int*   tpe = (const int*)d_in[1];
    const int*   Wq  = (const int*)d_in[2];
    const float* Sc  = (const float*)d_in[3];
    const float* Zr  = (const float*)d_in[4];
    float*       Y   = (float*)d_out;

    xcvt_k<<<NTOK, 256>>>(X);
    wcvt_k<<<(NE * KDIM * ODIM) / (256 * 8), 256>>>(Wq, Sc, tpe);
    dim3 gB(ODIM / 128, NTOK / 128);
    yinit_k<<<gB, 256>>>(tpe, Sc, Zr, Y);
    dim3 gM(ODIM / BN, NTOK / BM);                         // 44 x 16
    hqq_main<<<gM, 256>>>(tpe, Y);
}